// round 4
// baseline (speedup 1.0000x reference)
#include <cuda_runtime.h>
#include <math.h>

// x:[32,512,56,56] f32, w1:[32,512], w2:[512,32]
// out = concat(scaled [32,512,56,56], comp [32,512])

#define B 32
#define C 512
#define CR 32
#define HW 3136
#define HW4 784
#define BC (B*C)           // 16384
#define NTOT (B*C*HW)
#define N4 (NTOT/4)        // 12845056
#define N8 (N4/2)          // 6422528
#define APPLY_BLOCKS (N8/256)  // 25088 exactly

__device__ float g_y[BC];
__device__ float g_gate[BC];

// ---------------------------------------------------------------------------
// Kernel 1: y[bc] = mean(x[bc,:]). One WARP per bc, 8 warps/block.
// DEFAULT cache policy on purpose: leave the tail of x resident in L2 so the
// apply pass (which walks x in reverse) hits it.
// ---------------------------------------------------------------------------
__global__ __launch_bounds__(256) void k_reduce_mean(const float* __restrict__ x) {
    const int warp = threadIdx.x >> 5;
    const int lane = threadIdx.x & 31;
    const int bc = blockIdx.x * 8 + warp;
    const float4* __restrict__ xp = reinterpret_cast<const float4*>(x) + (size_t)bc * HW4;

    float s = 0.f;
    int j = lane;
    #pragma unroll 6
    for (int k = 0; k < 24; k++, j += 32) {
        float4 v = xp[j];
        s += (v.x + v.y) + (v.z + v.w);
    }
    if (lane < 16) {                       // 784 = 24*32 + 16
        float4 v = xp[768 + lane];
        s += (v.x + v.y) + (v.z + v.w);
    }
    #pragma unroll
    for (int o = 16; o > 0; o >>= 1)
        s += __shfl_xor_sync(0xFFFFFFFFu, s, o);
    if (lane == 0) g_y[bc] = s * (1.0f / HW);
}

// ---------------------------------------------------------------------------
// Kernel 2 (fused MLP): one block per b, 512 threads.
// Phase 1: h[r]=relu(sum_c y[b][c]*w1[r][c]); 16 warps, 2 r's per warp.
// Phase 2: g[b][c]=sigmoid(sum_r h[r]*w2[c][r]); one thread per c.
//          comp[b][c]=y[b][c]*(1-g)  (gate constant over H,W).
// ---------------------------------------------------------------------------
__global__ __launch_bounds__(512) void k_mlp(const float* __restrict__ w1,
                                             const float* __restrict__ w2,
                                             float* __restrict__ comp_out) {
    __shared__ float y_s[C];
    __shared__ float h_s[CR];
    const int b = blockIdx.x;
    const int tid = threadIdx.x;

    y_s[tid] = g_y[b * C + tid];
    __syncthreads();

    const int warp = tid >> 5;
    const int lane = tid & 31;
    #pragma unroll
    for (int r2 = 0; r2 < 2; r2++) {
        const int r = warp * 2 + r2;
        const float* __restrict__ w1r = w1 + r * C;
        float acc = 0.f;
        #pragma unroll
        for (int c = lane; c < C; c += 32)
            acc += y_s[c] * w1r[c];
        #pragma unroll
        for (int o = 16; o > 0; o >>= 1)
            acc += __shfl_xor_sync(0xFFFFFFFFu, acc, o);
        if (lane == 0) h_s[r] = fmaxf(acc, 0.f);
    }
    __syncthreads();

    const int c = tid;
    const float4* __restrict__ w2c = reinterpret_cast<const float4*>(w2 + c * CR);
    float acc = 0.f;
    #pragma unroll
    for (int j = 0; j < 8; j++) {
        float4 w = w2c[j];
        acc += h_s[4*j+0] * w.x + h_s[4*j+1] * w.y + h_s[4*j+2] * w.z + h_s[4*j+3] * w.w;
    }
    const float g = 1.0f / (1.0f + expf(-acc));
    const int idx = b * C + c;
    g_gate[idx] = g;
    comp_out[idx] = y_s[c] * (1.0f - g);
}

// ---------------------------------------------------------------------------
// Kernel 3: scaled = x * gate[bc]. Two float4s per thread.
// REVERSE block order: first-scheduled blocks touch the highest addresses,
// which the reduce pass left resident in L2. x reads: __ldcs (last use).
// out stores: __stcs (evict-first, don't pollute L2).
// Grid is exactly N8/256 blocks — no tail, no bounds check.
// ---------------------------------------------------------------------------
__global__ __launch_bounds__(256) void k_apply_gate(const float* __restrict__ x,
                                                    float* __restrict__ out) {
    const int t = (APPLY_BLOCKS - 1 - blockIdx.x) * 256 + threadIdx.x;
    const int i = t * 2;                  // pair never straddles bc (HW4 even)
    const int bc = i / HW4;
    const float g = __ldg(&g_gate[bc]);

    const float4* __restrict__ xp = reinterpret_cast<const float4*>(x);
    float4* __restrict__ op = reinterpret_cast<float4*>(out);

    float4 v0 = __ldcs(&xp[i]);
    float4 v1 = __ldcs(&xp[i + 1]);
    v0.x *= g; v0.y *= g; v0.z *= g; v0.w *= g;
    v1.x *= g; v1.y *= g; v1.z *= g; v1.w *= g;
    __stcs(&op[i],     v0);
    __stcs(&op[i + 1], v1);
}

// ---------------------------------------------------------------------------
extern "C" void kernel_launch(void* const* d_in, const int* in_sizes, int n_in,
                              void* d_out, int out_size) {
    const float* x  = (const float*)d_in[0];
    const float* w1 = (const float*)d_in[1];
    const float* w2 = (const float*)d_in[2];
    float* out = (float*)d_out;

    float* scaled = out;
    float* comp   = out + NTOT;

    k_reduce_mean<<<BC / 8, 256>>>(x);
    k_mlp<<<B, 512>>>(w1, w2, comp);
    k_apply_gate<<<APPLY_BLOCKS, 256>>>(x, scaled);
}

// round 5
// speedup vs baseline: 1.1960x; 1.1960x over previous
#include <cuda_runtime.h>
#include <math.h>

// x:[32,512,56,56] f32, w1:[32,512], w2:[512,32]
// out = concat(scaled [32,512,56,56], comp [32,512])

#define B 32
#define C 512
#define CR 32
#define HW 3136
#define HW4 784
#define BC (B*C)            // 16384
#define NTOT (B*C*HW)
#define N4 (NTOT/4)         // 12845056
#define N16 (N4/4)          // 3211264  (4 float4s per thread)
#define APPLY_BLOCKS (N16/256)  // 12544 exactly

__device__ float g_y[BC];
__device__ float g_gate[BC];

// ---------------------------------------------------------------------------
// Kernel 1: y[bc] = mean(x[bc,:]). One WARP per bc, 8 warps/block.
// __ldcs: streaming read (R3-measured 6.14 TB/s, 77% of spec).
// ---------------------------------------------------------------------------
__global__ __launch_bounds__(256) void k_reduce_mean(const float* __restrict__ x) {
    const int warp = threadIdx.x >> 5;
    const int lane = threadIdx.x & 31;
    const int bc = blockIdx.x * 8 + warp;
    const float4* __restrict__ xp = reinterpret_cast<const float4*>(x) + (size_t)bc * HW4;

    float s = 0.f;
    int j = lane;
    #pragma unroll 6
    for (int k = 0; k < 24; k++, j += 32) {
        float4 v = __ldcs(&xp[j]);
        s += (v.x + v.y) + (v.z + v.w);
    }
    if (lane < 16) {                       // 784 = 24*32 + 16
        float4 v = __ldcs(&xp[768 + lane]);
        s += (v.x + v.y) + (v.z + v.w);
    }
    #pragma unroll
    for (int o = 16; o > 0; o >>= 1)
        s += __shfl_xor_sync(0xFFFFFFFFu, s, o);
    if (lane == 0) g_y[bc] = s * (1.0f / HW);
}

// ---------------------------------------------------------------------------
// Kernel 2 (fused MLP): one block per b, 512 threads.
// Phase 1: h[r]=relu(sum_c y[b][c]*w1[r][c]); 16 warps, 2 r's per warp.
// Phase 2: g[b][c]=sigmoid(sum_r h[r]*w2[c][r]); one thread per c.
//          comp[b][c]=y[b][c]*(1-g)  (gate constant over H,W).
// ---------------------------------------------------------------------------
__global__ __launch_bounds__(512) void k_mlp(const float* __restrict__ w1,
                                             const float* __restrict__ w2,
                                             float* __restrict__ comp_out) {
    __shared__ float y_s[C];
    __shared__ float h_s[CR];
    const int b = blockIdx.x;
    const int tid = threadIdx.x;

    y_s[tid] = g_y[b * C + tid];
    __syncthreads();

    const int warp = tid >> 5;
    const int lane = tid & 31;
    #pragma unroll
    for (int r2 = 0; r2 < 2; r2++) {
        const int r = warp * 2 + r2;
        const float* __restrict__ w1r = w1 + r * C;
        float acc = 0.f;
        #pragma unroll
        for (int c = lane; c < C; c += 32)
            acc += y_s[c] * w1r[c];
        #pragma unroll
        for (int o = 16; o > 0; o >>= 1)
            acc += __shfl_xor_sync(0xFFFFFFFFu, acc, o);
        if (lane == 0) h_s[r] = fmaxf(acc, 0.f);
    }
    __syncthreads();

    const int c = tid;
    const float4* __restrict__ w2c = reinterpret_cast<const float4*>(w2 + c * CR);
    float acc = 0.f;
    #pragma unroll
    for (int j = 0; j < 8; j++) {
        float4 w = w2c[j];
        acc += h_s[4*j+0] * w.x + h_s[4*j+1] * w.y + h_s[4*j+2] * w.z + h_s[4*j+3] * w.w;
    }
    const float g = 1.0f / (1.0f + expf(-acc));
    const int idx = b * C + c;
    g_gate[idx] = g;
    comp_out[idx] = y_s[c] * (1.0f - g);
}

// ---------------------------------------------------------------------------
// Kernel 3: scaled = x * gate[bc]. FOUR consecutive float4s per thread
// (784 % 4 == 0, so a group of 4 never straddles a channel boundary -> one
// gate fetch per 16 elements). Forward linear order. Streaming hints.
// Grid exact: no bounds check.
// ---------------------------------------------------------------------------
__global__ __launch_bounds__(256) void k_apply_gate(const float* __restrict__ x,
                                                    float* __restrict__ out) {
    const int t = blockIdx.x * 256 + threadIdx.x;
    const int i = t * 4;
    const int bc = i / HW4;
    const float g = __ldg(&g_gate[bc]);

    const float4* __restrict__ xp = reinterpret_cast<const float4*>(x);
    float4* __restrict__ op = reinterpret_cast<float4*>(out);

    float4 v0 = __ldcs(&xp[i]);
    float4 v1 = __ldcs(&xp[i + 1]);
    float4 v2 = __ldcs(&xp[i + 2]);
    float4 v3 = __ldcs(&xp[i + 3]);
    v0.x *= g; v0.y *= g; v0.z *= g; v0.w *= g;
    v1.x *= g; v1.y *= g; v1.z *= g; v1.w *= g;
    v2.x *= g; v2.y *= g; v2.z *= g; v2.w *= g;
    v3.x *= g; v3.y *= g; v3.z *= g; v3.w *= g;
    __stcs(&op[i],     v0);
    __stcs(&op[i + 1], v1);
    __stcs(&op[i + 2], v2);
    __stcs(&op[i + 3], v3);
}

// ---------------------------------------------------------------------------
extern "C" void kernel_launch(void* const* d_in, const int* in_sizes, int n_in,
                              void* d_out, int out_size) {
    const float* x  = (const float*)d_in[0];
    const float* w1 = (const float*)d_in[1];
    const float* w2 = (const float*)d_in[2];
    float* out = (float*)d_out;

    float* scaled = out;
    float* comp   = out + NTOT;

    k_reduce_mean<<<BC / 8, 256>>>(x);
    k_mlp<<<B, 512>>>(w1, w2, comp);
    k_apply_gate<<<APPLY_BLOCKS, 256>>>(x, scaled);
}

// round 6
// speedup vs baseline: 1.3252x; 1.1080x over previous
#include <cuda_runtime.h>
#include <math.h>

// x:[32,512,56,56] f32, w1:[32,512], w2:[512,32]
// out = concat(scaled [32,512,56,56], comp [32,512])

#define B 32
#define C 512
#define CR 32
#define HW 3136
#define HW4 784
#define BC (B*C)            // 16384
#define NTOT (B*C*HW)
#define N4 (NTOT/4)         // 12845056 float4s
#define HALF4 (N4/2)        // 6422528 (= 8192*784, channel-aligned)
#define APPLY_BLOCKS (HALF4/256)   // 25088 exactly

__device__ float g_y[BC];
__device__ float g_gate[BC];

// ---------------------------------------------------------------------------
// Kernel 1: y[bc] = mean(x[bc,:]). One WARP per bc, 8 warps/block.
// Lane-strided float4 loads are warp-coalesced; __ldcs (no reuse).
// Measured: ~35 us, 6.0-6.1 TB/s.
// ---------------------------------------------------------------------------
__global__ __launch_bounds__(256) void k_reduce_mean(const float* __restrict__ x) {
    const int warp = threadIdx.x >> 5;
    const int lane = threadIdx.x & 31;
    const int bc = blockIdx.x * 8 + warp;
    const float4* __restrict__ xp = reinterpret_cast<const float4*>(x) + (size_t)bc * HW4;

    float s = 0.f;
    int j = lane;
    #pragma unroll 6
    for (int k = 0; k < 24; k++, j += 32) {
        float4 v = __ldcs(&xp[j]);
        s += (v.x + v.y) + (v.z + v.w);
    }
    if (lane < 16) {                       // 784 = 24*32 + 16
        float4 v = __ldcs(&xp[768 + lane]);
        s += (v.x + v.y) + (v.z + v.w);
    }
    #pragma unroll
    for (int o = 16; o > 0; o >>= 1)
        s += __shfl_xor_sync(0xFFFFFFFFu, s, o);
    if (lane == 0) g_y[bc] = s * (1.0f / HW);
}

// ---------------------------------------------------------------------------
// Kernel 2 (fused MLP): one block per b, 512 threads.
// Phase 1: h[r]=relu(sum_c y[b][c]*w1[r][c]); 16 warps, 2 r's per warp.
// Phase 2: g[b][c]=sigmoid(sum_r h[r]*w2[c][r]); one thread per c.
//          comp[b][c]=y[b][c]*(1-g)  (gate constant over H,W).
// ---------------------------------------------------------------------------
__global__ __launch_bounds__(512) void k_mlp(const float* __restrict__ w1,
                                             const float* __restrict__ w2,
                                             float* __restrict__ comp_out) {
    __shared__ float y_s[C];
    __shared__ float h_s[CR];
    const int b = blockIdx.x;
    const int tid = threadIdx.x;

    y_s[tid] = g_y[b * C + tid];
    __syncthreads();

    const int warp = tid >> 5;
    const int lane = tid & 31;
    #pragma unroll
    for (int r2 = 0; r2 < 2; r2++) {
        const int r = warp * 2 + r2;
        const float* __restrict__ w1r = w1 + r * C;
        float acc = 0.f;
        #pragma unroll
        for (int c = lane; c < C; c += 32)
            acc += y_s[c] * w1r[c];
        #pragma unroll
        for (int o = 16; o > 0; o >>= 1)
            acc += __shfl_xor_sync(0xFFFFFFFFu, acc, o);
        if (lane == 0) h_s[r] = fmaxf(acc, 0.f);
    }
    __syncthreads();

    const int c = tid;
    const float4* __restrict__ w2c = reinterpret_cast<const float4*>(w2 + c * CR);
    float acc = 0.f;
    #pragma unroll
    for (int j = 0; j < 8; j++) {
        float4 w = w2c[j];
        acc += h_s[4*j+0] * w.x + h_s[4*j+1] * w.y + h_s[4*j+2] * w.z + h_s[4*j+3] * w.w;
    }
    const float g = 1.0f / (1.0f + expf(-acc));
    const int idx = b * C + c;
    g_gate[idx] = g;
    comp_out[idx] = y_s[c] * (1.0f - g);
}

// ---------------------------------------------------------------------------
// Kernel 3: scaled = x * gate[bc]. TWO fully-coalesced streams per thread:
// index i (first half of x) and i + HALF4 (second half). Consecutive lanes ->
// consecutive float4s in BOTH streams (4 lines per warp-load, the minimum).
// HALF4 is a multiple of HW4, so both halves are channel-aligned.
// Exact grid, no bounds check. Streaming hints (zero reuse).
// ---------------------------------------------------------------------------
__global__ __launch_bounds__(256) void k_apply_gate(const float* __restrict__ x,
                                                    float* __restrict__ out) {
    const int i0 = blockIdx.x * 256 + threadIdx.x;
    const int i1 = i0 + HALF4;

    const float4* __restrict__ xp = reinterpret_cast<const float4*>(x);
    float4* __restrict__ op = reinterpret_cast<float4*>(out);

    const float g0 = __ldg(&g_gate[i0 / HW4]);
    const float g1 = __ldg(&g_gate[i1 / HW4]);

    float4 v0 = __ldcs(&xp[i0]);
    float4 v1 = __ldcs(&xp[i1]);
    v0.x *= g0; v0.y *= g0; v0.z *= g0; v0.w *= g0;
    v1.x *= g1; v1.y *= g1; v1.z *= g1; v1.w *= g1;
    __stcs(&op[i0], v0);
    __stcs(&op[i1], v1);
}

// ---------------------------------------------------------------------------
extern "C" void kernel_launch(void* const* d_in, const int* in_sizes, int n_in,
                              void* d_out, int out_size) {
    const float* x  = (const float*)d_in[0];
    const float* w1 = (const float*)d_in[1];
    const float* w2 = (const float*)d_in[2];
    float* out = (float*)d_out;

    float* scaled = out;
    float* comp   = out + NTOT;

    k_reduce_mean<<<BC / 8, 256>>>(x);
    k_mlp<<<B, 512>>>(w1, w2, comp);
    k_apply_gate<<<APPLY_BLOCKS, 256>>>(x, scaled);
}